// round 5
// baseline (speedup 1.0000x reference)
#include <cuda_runtime.h>
#include <math.h>

// Fused: binarized-conv(3x3,Cin=1,Cout=32,SAME) + global-avg-pool + dense(32->10) + softmax.
// pooling commutes with conv: p[b,co] = conv_b[co] + (1/4096)*sum_k sign(w[k,co])*S[b,k],
// S[b,k] = 9 shifted sums from {total, row0, row63, col0, col63, 4 corners}.
// All weights prefetched at kernel top (overlapped with image loads); post-barrier
// epilogue is pure shared/register math.

#define B_TOTAL 512
#define HW 4096
#define NCO 32
#define NCLS 10

__global__ __launch_bounds__(256, 4)
void fused_bnn_kernel(const float* __restrict__ x,
                      const float* __restrict__ conv_w,   // [9,32]
                      const float* __restrict__ conv_b,   // [32]
                      const float* __restrict__ dense_w,  // [32,10]
                      const float* __restrict__ dense_b,  // [10]
                      float* __restrict__ out)            // [512,10]
{
    __shared__ float warpsum[5][8];
    __shared__ float corn[4];                 // x[0,0], x[0,63], x[63,0], x[63,63]
    __shared__ float s_dw[NCO * NCLS];        // dense_w staged (320 floats)

    const int b    = blockIdx.x;
    const int tid  = threadIdx.x;             // 256
    const int lane = tid & 31;
    const int wid  = tid >> 5;
    const unsigned FULL = 0xffffffffu;
    const float4* img4 = reinterpret_cast<const float4*>(x + (size_t)b * HW);

    // ---- issue all loads up front (image + weights overlap) ----
    float4 v0 = img4[tid];
    float4 v1 = img4[tid + 256];
    float4 v2 = img4[tid + 512];
    float4 v3 = img4[tid + 768];

    // Stage dense_w to shared (coalesced; threads 0..255 cover 320 entries in 2 steps).
    s_dw[tid >= 64 ? tid : tid] = dense_w[tid] * 0.0f + dense_w[tid]; // placeholder avoided below
    // (real staging below — keep simple, two strided stores)
    s_dw[tid] = dense_w[tid];
    if (tid < NCO * NCLS - 256) s_dw[tid + 256] = dense_w[tid + 256];

    // Warp 0 prefetches conv weights/biases into registers.
    float wk0=0,wk1=0,wk2=0,wk3=0,wk4=0,wk5=0,wk6=0,wk7=0,wk8=0, cb=0, db=0;
    if (wid == 0) {
        wk0 = conv_w[0*NCO + lane]; wk1 = conv_w[1*NCO + lane]; wk2 = conv_w[2*NCO + lane];
        wk3 = conv_w[3*NCO + lane]; wk4 = conv_w[4*NCO + lane]; wk5 = conv_w[5*NCO + lane];
        wk6 = conv_w[6*NCO + lane]; wk7 = conv_w[7*NCO + lane]; wk8 = conv_w[8*NCO + lane];
        cb  = conv_b[lane];
        db  = (lane < NCLS) ? dense_b[lane] : 0.0f;
    }

    // ---- per-thread partial stats ----
    // float4 f covers floats [4f,4f+4); row=f>>4; col0 iff (f&15)==0 (.x); col63 iff (f&15)==15 (.w)
    float s0 = (v0.x + v0.y) + (v0.z + v0.w);
    float s1 = (v1.x + v1.y) + (v1.z + v1.w);
    float s2 = (v2.x + v2.y) + (v2.z + v2.w);
    float s3 = (v3.x + v3.y) + (v3.z + v3.w);

    float T   = (s0 + s1) + (s2 + s3);
    float R0  = (tid < 16)         ? s0 : 0.0f;
    float R63 = (tid >= 240)       ? s3 : 0.0f;
    float C0  = ((tid & 15) == 0)  ? (v0.x + v1.x) + (v2.x + v3.x) : 0.0f;
    float C63 = ((tid & 15) == 15) ? (v0.w + v1.w) + (v2.w + v3.w) : 0.0f;

    if (tid == 0)   corn[0] = v0.x;   // x[0,0]
    if (tid == 15)  corn[1] = v0.w;   // x[0,63]
    if (tid == 240) corn[2] = v3.x;   // x[63,0]
    if (tid == 255) corn[3] = v3.w;   // x[63,63]

    #pragma unroll
    for (int off = 16; off > 0; off >>= 1) {
        T   += __shfl_down_sync(FULL, T,   off);
        R0  += __shfl_down_sync(FULL, R0,  off);
        R63 += __shfl_down_sync(FULL, R63, off);
        C0  += __shfl_down_sync(FULL, C0,  off);
        C63 += __shfl_down_sync(FULL, C63, off);
    }
    if (lane == 0) {
        warpsum[0][wid] = T;  warpsum[1][wid] = R0;  warpsum[2][wid] = R63;
        warpsum[3][wid] = C0; warpsum[4][wid] = C63;
    }
    __syncthreads();   // the only barrier (also covers s_dw staging)

    if (wid != 0) return;   // warp 0 finishes; all operands now in regs/shared

    float stat = 0.0f;
    if (lane < 5) {
        #pragma unroll
        for (int i = 0; i < 8; i++) stat += warpsum[lane][i];
    }
    float t   = __shfl_sync(FULL, stat, 0);
    float r0  = __shfl_sync(FULL, stat, 1);
    float r63 = __shfl_sync(FULL, stat, 2);
    float c0  = __shfl_sync(FULL, stat, 3);
    float c63 = __shfl_sync(FULL, stat, 4);
    float x00 = corn[0], x0e = corn[1], xe0 = corn[2], xee = corn[3];

    float S0 = t - r63 - c63 + xee, S1 = t - r63, S2 = t - r63 - c0 + xe0;
    float S3 = t - c63,             S4 = t,       S5 = t - c0;
    float S6 = t - r0  - c63 + x0e, S7 = t - r0,  S8 = t - r0  - c0 + x00;

    // p[lane] = conv_b + (1/4096) * sum_k sign(conv_w[k,lane]) * S[k]
    float acc = (wk0 >= 0.f ? S0 : -S0) + (wk1 >= 0.f ? S1 : -S1)
              + (wk2 >= 0.f ? S2 : -S2) + (wk3 >= 0.f ? S3 : -S3)
              + (wk4 >= 0.f ? S4 : -S4) + (wk5 >= 0.f ? S5 : -S5)
              + (wk6 >= 0.f ? S6 : -S6) + (wk7 >= 0.f ? S7 : -S7)
              + (wk8 >= 0.f ? S8 : -S8);
    float p = cb + acc * (1.0f / (float)HW);

    // logits: lanes 0..9; dense_w from shared
    float logit = db;
    #pragma unroll
    for (int co = 0; co < NCO; co++) {
        float pc = __shfl_sync(FULL, p, co);
        if (lane < NCLS) logit += pc * s_dw[co * NCLS + lane];
    }

    // softmax over lanes 0..9 (4-level butterflies, neutral fill)
    float m = (lane < NCLS) ? logit : -INFINITY;
    #pragma unroll
    for (int off = 8; off > 0; off >>= 1)
        m = fmaxf(m, __shfl_xor_sync(FULL, m, off));
    float e = (lane < NCLS) ? __expf(logit - m) : 0.0f;
    float d = e;
    #pragma unroll
    for (int off = 8; off > 0; off >>= 1)
        d += __shfl_xor_sync(FULL, d, off);

    if (lane < NCLS) out[b * NCLS + lane] = __fdividef(e, d);
}

extern "C" void kernel_launch(void* const* d_in, const int* in_sizes, int n_in,
                              void* d_out, int out_size) {
    const float* x       = (const float*)d_in[0];
    const float* conv_w  = (const float*)d_in[1];
    const float* conv_b  = (const float*)d_in[2];
    const float* dense_w = (const float*)d_in[3];
    const float* dense_b = (const float*)d_in[4];
    float* out = (float*)d_out;
    (void)in_sizes; (void)n_in; (void)out_size;

    fused_bnn_kernel<<<B_TOTAL, 256>>>(x, conv_w, conv_b, dense_w, dense_b, out);
}

// round 6
// speedup vs baseline: 1.3527x; 1.3527x over previous
#include <cuda_runtime.h>
#include <math.h>

// Fused: binarized-conv(3x3,Cin=1,Cout=32,SAME) + global-avg-pool + dense(32->10) + softmax.
// pooling commutes with conv: p[b,co] = conv_b[co] + (1/4096)*sum_k sign(w[k,co])*S[b,k],
// S[b,k] = 9 shifted sums from {total, row0, row63, col0, col63, 4 corners}.
// Warp 0 stages all weights to smem pre-barrier (overlapped with image DRAM waits);
// post-barrier epilogue is smem/register-only, dense done transposed so softmax is
// pure register math.

#define B_TOTAL 512
#define HW 4096
#define NCO 32
#define NCLS 10

__global__ __launch_bounds__(256, 4)
void fused_bnn_kernel(const float* __restrict__ x,
                      const float* __restrict__ conv_w,   // [9,32]
                      const float* __restrict__ conv_b,   // [32]
                      const float* __restrict__ dense_w,  // [32,10]
                      const float* __restrict__ dense_b,  // [10]
                      float* __restrict__ out)            // [512,10]
{
    __shared__ float warpsum[5][8];
    __shared__ float corn[4];            // x[0,0], x[0,63], x[63,0], x[63,63]
    __shared__ float s_cw[9 * NCO];
    __shared__ float s_cb[NCO];
    __shared__ float s_dw[NCO * NCLS];
    __shared__ float s_db[NCLS];

    const int b    = blockIdx.x;
    const int tid  = threadIdx.x;        // 256
    const int lane = tid & 31;
    const int wid  = tid >> 5;
    const unsigned FULL = 0xffffffffu;
    const float4* img4 = reinterpret_cast<const float4*>(x + (size_t)b * HW);

    // ---- image loads first (the DRAM stream) ----
    float4 v0 = img4[tid];
    float4 v1 = img4[tid + 256];
    float4 v2 = img4[tid + 512];
    float4 v3 = img4[tid + 768];

    // ---- warp 0 only: stage weights to smem (L2-resident, overlaps DRAM waits) ----
    if (wid == 0) {
        #pragma unroll
        for (int k = 0; k < 9; k++) s_cw[k * NCO + lane] = conv_w[k * NCO + lane];
        s_cb[lane] = conv_b[lane];
        #pragma unroll
        for (int n = 0; n < NCLS; n++) s_dw[lane * NCLS + n] = dense_w[lane * NCLS + n];
        if (lane < NCLS) s_db[lane] = dense_b[lane];
    }

    // ---- per-thread partial stats ----
    // float4 f covers floats [4f,4f+4); row=f>>4; col0 iff (f&15)==0 (.x); col63 iff (f&15)==15 (.w)
    float s0 = (v0.x + v0.y) + (v0.z + v0.w);
    float s1 = (v1.x + v1.y) + (v1.z + v1.w);
    float s2 = (v2.x + v2.y) + (v2.z + v2.w);
    float s3 = (v3.x + v3.y) + (v3.z + v3.w);

    float T   = (s0 + s1) + (s2 + s3);
    float R0  = (tid < 16)         ? s0 : 0.0f;
    float R63 = (tid >= 240)       ? s3 : 0.0f;
    float C0  = ((tid & 15) == 0)  ? (v0.x + v1.x) + (v2.x + v3.x) : 0.0f;
    float C63 = ((tid & 15) == 15) ? (v0.w + v1.w) + (v2.w + v3.w) : 0.0f;

    if (tid == 0)   corn[0] = v0.x;   // x[0,0]
    if (tid == 15)  corn[1] = v0.w;   // x[0,63]
    if (tid == 240) corn[2] = v3.x;   // x[63,0]
    if (tid == 255) corn[3] = v3.w;   // x[63,63]

    #pragma unroll
    for (int off = 16; off > 0; off >>= 1) {
        T   += __shfl_down_sync(FULL, T,   off);
        R0  += __shfl_down_sync(FULL, R0,  off);
        R63 += __shfl_down_sync(FULL, R63, off);
        C0  += __shfl_down_sync(FULL, C0,  off);
        C63 += __shfl_down_sync(FULL, C63, off);
    }
    if (lane == 0) {
        warpsum[0][wid] = T;  warpsum[1][wid] = R0;  warpsum[2][wid] = R63;
        warpsum[3][wid] = C0; warpsum[4][wid] = C63;
    }
    __syncthreads();   // the only barrier (covers weight staging too)

    if (wid != 0) return;   // warp 0 finishes; operands in smem/regs only

    float stat = 0.0f;
    if (lane < 5) {
        #pragma unroll
        for (int i = 0; i < 8; i++) stat += warpsum[lane][i];
    }
    float t   = __shfl_sync(FULL, stat, 0);
    float r0  = __shfl_sync(FULL, stat, 1);
    float r63 = __shfl_sync(FULL, stat, 2);
    float c0  = __shfl_sync(FULL, stat, 3);
    float c63 = __shfl_sync(FULL, stat, 4);
    float x00 = corn[0], x0e = corn[1], xe0 = corn[2], xee = corn[3];

    float S0 = t - r63 - c63 + xee, S1 = t - r63, S2 = t - r63 - c0 + xe0;
    float S3 = t - c63,             S4 = t,       S5 = t - c0;
    float S6 = t - r0  - c63 + x0e, S7 = t - r0,  S8 = t - r0  - c0 + x00;

    // Channel co = lane: p = conv_b + (1/4096) * sum_k sign(conv_w[k,co]) * S[k]
    float acc = (s_cw[0*NCO+lane] >= 0.f ? S0 : -S0)
              + (s_cw[1*NCO+lane] >= 0.f ? S1 : -S1)
              + (s_cw[2*NCO+lane] >= 0.f ? S2 : -S2)
              + (s_cw[3*NCO+lane] >= 0.f ? S3 : -S3)
              + (s_cw[4*NCO+lane] >= 0.f ? S4 : -S4)
              + (s_cw[5*NCO+lane] >= 0.f ? S5 : -S5)
              + (s_cw[6*NCO+lane] >= 0.f ? S6 : -S6)
              + (s_cw[7*NCO+lane] >= 0.f ? S7 : -S7)
              + (s_cw[8*NCO+lane] >= 0.f ? S8 : -S8);
    float p = s_cb[lane] + acc * (1.0f / (float)HW);

    // Transposed dense: lane=co contributes p * dense_w[co][n] into 10 accumulators,
    // then 10 parallel butterflies -> every lane holds all 10 logits.
    float lg[NCLS];
    #pragma unroll
    for (int n = 0; n < NCLS; n++) lg[n] = p * s_dw[lane * NCLS + n];
    #pragma unroll
    for (int off = 16; off > 0; off >>= 1) {
        #pragma unroll
        for (int n = 0; n < NCLS; n++) lg[n] += __shfl_xor_sync(FULL, lg[n], off);
    }
    #pragma unroll
    for (int n = 0; n < NCLS; n++) lg[n] += s_db[n];

    // Softmax entirely in registers (every lane redundantly).
    float m = lg[0];
    #pragma unroll
    for (int n = 1; n < NCLS; n++) m = fmaxf(m, lg[n]);
    float e[NCLS], d = 0.0f;
    #pragma unroll
    for (int n = 0; n < NCLS; n++) { e[n] = __expf(lg[n] - m); d += e[n]; }
    float inv = __fdividef(1.0f, d);

    if (lane < NCLS) out[b * NCLS + lane] = e[lane] * inv;
}

extern "C" void kernel_launch(void* const* d_in, const int* in_sizes, int n_in,
                              void* d_out, int out_size) {
    const float* x       = (const float*)d_in[0];
    const float* conv_w  = (const float*)d_in[1];
    const float* conv_b  = (const float*)d_in[2];
    const float* dense_w = (const float*)d_in[3];
    const float* dense_b = (const float*)d_in[4];
    float* out = (float*)d_out;
    (void)in_sizes; (void)n_in; (void)out_size;

    fused_bnn_kernel<<<B_TOTAL, 256>>>(x, conv_w, conv_b, dense_w, dense_b, out);
}